// round 1
// baseline (speedup 1.0000x reference)
#include <cuda_runtime.h>

// BinaryBiaffine2: scores = leaky(X@W + b) @ Wc per branch, then broadcast add.
// X: [16384, 1024] fp32, W_dep/W_head: [1024, 500], Wc: [1000, 2], out: [16,1024,1024,2].

#define D_DIM 1024
#define M_DIM 500
#define NC    1000      // combined columns (dep 0..499, head 500..999)
#define BM    128
#define BN    128
#define BK    16
#define NTHREADS 256
#define NEG   0.01f
#define MAXBL 16384

// scores scratch: [0 .. 2*MAXBL) = dep (n*2+c), [2*MAXBL ..) = head
__device__ float g_scores[MAXBL * 4];

typedef unsigned long long u64;

__device__ __forceinline__ u64 pk2(float x, float y) {
    u64 r; asm("mov.b64 %0, {%1, %2};" : "=l"(r) : "f"(x), "f"(y)); return r;
}
__device__ __forceinline__ void fma2(u64 &d, u64 a, u64 b) {
    asm("fma.rn.f32x2 %0, %1, %2, %0;" : "+l"(d) : "l"(a), "l"(b));
}
__device__ __forceinline__ float2 unpk2(u64 v) {
    float2 f; asm("mov.b64 {%0, %1}, %2;" : "=f"(f.x), "=f"(f.y) : "l"(v)); return f;
}

__global__ void zero_scores(int count) {
    int i = blockIdx.x * blockDim.x + threadIdx.x;
    if (i < count) g_scores[i] = 0.0f;
}

__global__ __launch_bounds__(NTHREADS, 2)
void gemm_scores(const float* __restrict__ X,
                 const float* __restrict__ Wd, const float* __restrict__ bd,
                 const float* __restrict__ Wh, const float* __restrict__ bh,
                 const float* __restrict__ Wc)
{
    __shared__ float Xs[BK][BM];
    __shared__ float Ws[BK][BN];

    const int tid     = threadIdx.x;
    const int colbase = blockIdx.x * BN;       // combined m' base
    const int R       = blockIdx.y * BM;       // row base in [0, BL)

    const int trow = tid >> 4;                 // 0..15 (8 rows each)
    const int tcol = tid & 15;                 // 0..15 (8 cols each)

    // X tile load map: 2 float4 per thread, 4 threads per row quad
    const int xr0 = tid >> 2;                  // 0..63
    const int xq  = (tid & 3) << 2;            // 0,4,8,12
    // W tile load map: 1 float4 per thread per pass, 32 threads per k-row
    const int wk0 = tid >> 5;                  // 0..7
    const int wcc = (tid & 31) << 2;           // 0..124
    const int mgW = colbase + wcc;             // fixed per thread

    u64 acc[8][4];
    #pragma unroll
    for (int i = 0; i < 8; ++i)
        #pragma unroll
        for (int j = 0; j < 4; ++j) acc[i][j] = 0ull;

    float4 xreg[2], wreg[2];

    // prefetch kt = 0
    #pragma unroll
    for (int pass = 0; pass < 2; ++pass) {
        int row = xr0 + pass * 64;
        xreg[pass] = *reinterpret_cast<const float4*>(&X[(size_t)(R + row) * D_DIM + xq]);
        int d = wk0 + pass * 8;
        if (mgW < M_DIM)      wreg[pass] = *reinterpret_cast<const float4*>(&Wd[(size_t)d * M_DIM + mgW]);
        else if (mgW < NC)    wreg[pass] = *reinterpret_cast<const float4*>(&Wh[(size_t)d * M_DIM + (mgW - M_DIM)]);
        else                  wreg[pass] = make_float4(0.f, 0.f, 0.f, 0.f);
    }

    const int KT = D_DIM / BK;                 // 64
    for (int kt = 0; kt < KT; ++kt) {
        // stage prefetched regs into smem
        #pragma unroll
        for (int pass = 0; pass < 2; ++pass) {
            float4 v = xreg[pass];
            int row = xr0 + pass * 64;
            Xs[xq + 0][row] = v.x;
            Xs[xq + 1][row] = v.y;
            Xs[xq + 2][row] = v.z;
            Xs[xq + 3][row] = v.w;
            *reinterpret_cast<float4*>(&Ws[wk0 + pass * 8][wcc]) = wreg[pass];
        }
        __syncthreads();

        // prefetch next tile (LDG latency overlapped with compute below)
        if (kt + 1 < KT) {
            const int ktn = kt + 1;
            #pragma unroll
            for (int pass = 0; pass < 2; ++pass) {
                int row = xr0 + pass * 64;
                xreg[pass] = *reinterpret_cast<const float4*>(
                    &X[(size_t)(R + row) * D_DIM + ktn * BK + xq]);
                int d = ktn * BK + wk0 + pass * 8;
                if (mgW < M_DIM)   wreg[pass] = *reinterpret_cast<const float4*>(&Wd[(size_t)d * M_DIM + mgW]);
                else if (mgW < NC) wreg[pass] = *reinterpret_cast<const float4*>(&Wh[(size_t)d * M_DIM + (mgW - M_DIM)]);
                else               wreg[pass] = make_float4(0.f, 0.f, 0.f, 0.f);
            }
        }

        // compute: 16 k-steps, 8x8 tile per thread via packed f32x2 FMA
        #pragma unroll
        for (int k = 0; k < BK; ++k) {
            float4 a0 = *reinterpret_cast<const float4*>(&Xs[k][trow * 8]);
            float4 a1 = *reinterpret_cast<const float4*>(&Xs[k][trow * 8 + 4]);
            const u64* bp = reinterpret_cast<const u64*>(&Ws[k][tcol * 8]);
            u64 b0 = bp[0], b1 = bp[1], b2 = bp[2], b3 = bp[3];
            float av[8] = {a0.x, a0.y, a0.z, a0.w, a1.x, a1.y, a1.z, a1.w};
            #pragma unroll
            for (int tm = 0; tm < 8; ++tm) {
                u64 ap = pk2(av[tm], av[tm]);
                fma2(acc[tm][0], ap, b0);
                fma2(acc[tm][1], ap, b1);
                fma2(acc[tm][2], ap, b2);
                fma2(acc[tm][3], ap, b3);
            }
        }
        __syncthreads();
    }

    // ---- epilogue: bias + leaky_relu + Wc reduction -> per-row scores ----
    float biasv[8], wc0v[8], wc1v[8];
    bool  depf[8];
    #pragma unroll
    for (int j = 0; j < 8; ++j) {
        int mg = colbase + tcol * 8 + j;
        if (mg < M_DIM) {
            biasv[j] = bd[mg]; depf[j] = true;
            wc0v[j] = Wc[mg * 2]; wc1v[j] = Wc[mg * 2 + 1];
        } else if (mg < NC) {
            biasv[j] = bh[mg - M_DIM]; depf[j] = false;
            wc0v[j] = Wc[mg * 2]; wc1v[j] = Wc[mg * 2 + 1];
        } else {
            biasv[j] = 0.f; depf[j] = false; wc0v[j] = 0.f; wc1v[j] = 0.f;
        }
    }
    const bool hasDep  = (colbase < M_DIM);
    const bool hasHead = (colbase + BN > M_DIM);

    float* ds = g_scores;
    float* hs = g_scores + 2 * MAXBL;

    #pragma unroll
    for (int tm = 0; tm < 8; ++tm) {
        float pd0 = 0.f, pd1 = 0.f, ph0 = 0.f, ph1 = 0.f;
        #pragma unroll
        for (int p = 0; p < 4; ++p) {
            float2 hv = unpk2(acc[tm][p]);
            #pragma unroll
            for (int e = 0; e < 2; ++e) {
                int j = p * 2 + e;
                float h = (e ? hv.y : hv.x) + biasv[j];
                h = h > 0.f ? h : NEG * h;
                if (depf[j]) { pd0 += h * wc0v[j]; pd1 += h * wc1v[j]; }
                else         { ph0 += h * wc0v[j]; ph1 += h * wc1v[j]; }
            }
        }
        // reduce over the 16 threads (half-warp) sharing this row group
        #pragma unroll
        for (int off = 8; off >= 1; off >>= 1) {
            pd0 += __shfl_xor_sync(0xffffffffu, pd0, off);
            pd1 += __shfl_xor_sync(0xffffffffu, pd1, off);
            ph0 += __shfl_xor_sync(0xffffffffu, ph0, off);
            ph1 += __shfl_xor_sync(0xffffffffu, ph1, off);
        }
        if (tcol == 0) {
            int row = R + trow * 8 + tm;
            if (hasDep)  { atomicAdd(&ds[row * 2 + 0], pd0); atomicAdd(&ds[row * 2 + 1], pd1); }
            if (hasHead) { atomicAdd(&hs[row * 2 + 0], ph0); atomicAdd(&hs[row * 2 + 1], ph1); }
        }
    }
}

// out[b, i, j, c] = dep[b,i,c] + head[b,j,c] + bc[c]
__global__ __launch_bounds__(256)
void bcast_kernel(const float* __restrict__ bc, float* __restrict__ out)
{
    const float* ds = g_scores;
    const float* hs = g_scores + 2 * MAXBL;
    const int n = blockIdx.x;                  // b*1024 + i
    const int b = n >> 10;
    const float base0 = ds[n * 2 + 0] + bc[0];
    const float base1 = ds[n * 2 + 1] + bc[1];
    const float4* hv = reinterpret_cast<const float4*>(hs + (size_t)b * 2048);
    float4* o = reinterpret_cast<float4*>(out + (size_t)n * 2048);
    #pragma unroll
    for (int t = threadIdx.x; t < 512; t += 256) {
        float4 h = hv[t];   // (head[j,0], head[j,1], head[j+1,0], head[j+1,1])
        o[t] = make_float4(base0 + h.x, base1 + h.y, base0 + h.z, base1 + h.w);
    }
}

extern "C" void kernel_launch(void* const* d_in, const int* in_sizes, int n_in,
                              void* d_out, int out_size)
{
    const float* X  = (const float*)d_in[0];
    const float* Wd = (const float*)d_in[1];
    const float* bd = (const float*)d_in[2];
    const float* Wh = (const float*)d_in[3];
    const float* bh = (const float*)d_in[4];
    const float* Wc = (const float*)d_in[5];
    const float* bc = (const float*)d_in[6];
    float* out = (float*)d_out;

    const int BL = in_sizes[0] / D_DIM;        // 16384

    zero_scores<<<(BL * 4 + 255) / 256, 256>>>(BL * 4);

    dim3 grid((NC + BN - 1) / BN, BL / BM);    // 8 x 128
    gemm_scores<<<grid, NTHREADS>>>(X, Wd, bd, Wh, bh, Wc);

    bcast_kernel<<<BL, 256>>>(bc, out);
}

// round 4
// speedup vs baseline: 2.6702x; 2.6702x over previous
#include <cuda_runtime.h>
#include <cuda_bf16.h>
#include <cstdint>

// BinaryBiaffine2 via warp-level bf16 mma.sync (sm_80+ PTX, compiles under compute_103):
// scores = leaky(X@W + b) @ Wc per branch, then broadcast pairwise add.
// fp32 -> 2-way bf16 split (hi+lo), 3 cross-term GEMMs fused as K-steps.

#define D_DIM 1024
#define M_DIM 500
#define NC    1000
#define NPAD  1024
#define BL_MAX 16384
#define NEG   0.01f

#define MT 128
#define NT 128
#define NCHUNK 32
#define GTHREADS 256

// dynamic smem layout
#define SM_A0 0
#define SM_A1 16384
#define SM_B0 32768
#define SM_B1 49152
#define SM_TAB 65536
#define SM_TOTAL (65536 + 2048)

// ---- scratch (static device globals; allocation-guard-safe) ----
__device__ __nv_bfloat16 g_Xi[(size_t)BL_MAX * 2048];   // [row][chunk*64 + half*32 + j]
__device__ __nv_bfloat16 g_Bi[(size_t)NPAD * 2048];     // [n][chunk*64 + half*32 + j]
__device__ float g_scores[BL_MAX * 4];                  // dep [0,2BL), head [2BL,4BL)

// ============================ PTX helpers ============================
__device__ __forceinline__ uint32_t smem_u32(const void* p) {
    uint32_t a;
    asm("{ .reg .u64 t; cvta.to.shared.u64 t, %1; cvt.u32.u64 %0, t; }" : "=r"(a) : "l"(p));
    return a;
}
#define SWZ128(x) ((x) ^ (((x) >> 3) & 0x70))

#define CP_ASYNC16(dst, src) \
    asm volatile("cp.async.cg.shared.global [%0], [%1], 16;" :: "r"(dst), "l"(src))
#define CP_COMMIT() asm volatile("cp.async.commit_group;" ::: "memory")
#define CP_WAIT1()  asm volatile("cp.async.wait_group 1;" ::: "memory")
#define CP_WAIT0()  asm volatile("cp.async.wait_group 0;" ::: "memory")

#define LDSM_X4(r0, r1, r2, r3, addr) \
    asm volatile("ldmatrix.sync.aligned.m8n8.x4.shared.b16 {%0,%1,%2,%3}, [%4];" \
                 : "=r"(r0), "=r"(r1), "=r"(r2), "=r"(r3) : "r"(addr))

#define MMA16816(d, a0, a1, a2, a3, b0, b1) \
    asm volatile("mma.sync.aligned.m16n8k16.row.col.f32.bf16.bf16.f32 " \
                 "{%0,%1,%2,%3}, {%4,%5,%6,%7}, {%8,%9}, {%0,%1,%2,%3};" \
                 : "+f"((d)[0]), "+f"((d)[1]), "+f"((d)[2]), "+f"((d)[3]) \
                 : "r"(a0), "r"(a1), "r"(a2), "r"(a3), "r"(b0), "r"(b1))

// ============================ converters ============================
__global__ void zero_scores(int count) {
    int i = blockIdx.x * blockDim.x + threadIdx.x;
    if (i < count) g_scores[i] = 0.0f;
}

__global__ void convX(const float* __restrict__ X) {
    size_t i = (size_t)blockIdx.x * blockDim.x + threadIdx.x;   // one float4 each
    const float4 v = reinterpret_cast<const float4*>(X)[i];
    size_t row = i >> 8;              // 256 float4 per 1024-col row
    int col = (int)(i & 255) * 4;
    int chunk = col >> 5, j = col & 31;
    __nv_bfloat16* o = g_Xi + row * 2048 + (size_t)chunk * 64 + j;

    __nv_bfloat16 h0 = __float2bfloat16(v.x), h1 = __float2bfloat16(v.y);
    __nv_bfloat16 h2 = __float2bfloat16(v.z), h3 = __float2bfloat16(v.w);
    __nv_bfloat16 l0 = __float2bfloat16(v.x - __bfloat162float(h0));
    __nv_bfloat16 l1 = __float2bfloat16(v.y - __bfloat162float(h1));
    __nv_bfloat16 l2 = __float2bfloat16(v.z - __bfloat162float(h2));
    __nv_bfloat16 l3 = __float2bfloat16(v.w - __bfloat162float(h3));

    __nv_bfloat162* oh = reinterpret_cast<__nv_bfloat162*>(o);
    __nv_bfloat162* ol = reinterpret_cast<__nv_bfloat162*>(o + 32);
    oh[0] = __nv_bfloat162(h0, h1); oh[1] = __nv_bfloat162(h2, h3);
    ol[0] = __nv_bfloat162(l0, l1); ol[1] = __nv_bfloat162(l2, l3);
}

// Transpose W_dep|W_head (fp32 [d][m]) into g_Bi [n][2048] bf16 hi|lo interleaved.
__global__ void convW(const float* __restrict__ Wd, const float* __restrict__ Wh) {
    __shared__ float t[32][33];
    const int m0 = blockIdx.x * 32, d0 = blockIdx.y * 32;
    const int tx = threadIdx.x, ty = threadIdx.y;     // 32 x 8
    #pragma unroll
    for (int yy = ty; yy < 32; yy += 8) {
        int m = m0 + tx, d = d0 + yy;
        float v = 0.0f;
        if (m < M_DIM)      v = Wd[(size_t)d * M_DIM + m];
        else if (m < NC)    v = Wh[(size_t)d * M_DIM + (m - M_DIM)];
        t[yy][tx] = v;
    }
    __syncthreads();
    #pragma unroll
    for (int yy = ty; yy < 32; yy += 8) {
        int n = m0 + yy;
        float v = t[tx][yy];
        __nv_bfloat16 h = __float2bfloat16(v);
        __nv_bfloat16 l = __float2bfloat16(v - __bfloat162float(h));
        size_t ob = (size_t)n * 2048 + (size_t)(d0 >> 5) * 64 + tx;
        g_Bi[ob] = h;
        g_Bi[ob + 32] = l;
    }
}

// ============================ HMMA GEMM + fused epilogue ============================
__global__ __launch_bounds__(GTHREADS, 2)
void gemm_mma(const float* __restrict__ bd, const float* __restrict__ bh,
              const float* __restrict__ Wc)
{
    extern __shared__ char dsm[];
    const uint32_t sbase = smem_u32(dsm);

    const int tid = threadIdx.x;
    const int wid = tid >> 5, lid = tid & 31;
    const int CB  = blockIdx.x * NT;      // n base
    const int R   = blockIdx.y * MT;      // m base

    float* sbias = reinterpret_cast<float*>(dsm + SM_TAB);
    float* sw0   = sbias + 128;
    float* sw1   = sbias + 256;
    int*   sdep  = reinterpret_cast<int*>(sbias + 384);

    if (tid < 128) {
        int n = CB + tid;
        float bias = 0.f, w0 = 0.f, w1 = 0.f; int dep = 0;
        if (n < M_DIM)      { bias = bd[n]; w0 = Wc[2*n]; w1 = Wc[2*n+1]; dep = 1; }
        else if (n < NC)    { bias = bh[n - M_DIM]; w0 = Wc[2*n]; w1 = Wc[2*n+1]; }
        sbias[tid] = bias; sw0[tid] = w0; sw1[tid] = w1; sdep[tid] = dep;
    }

    // cp.async load mapping: 4 chunks of 16B per array per thread
    const __nv_bfloat16* Ag = g_Xi + (size_t)R * 2048;
    const __nv_bfloat16* Bg = g_Bi + (size_t)CB * 2048;

    // ldmatrix lane address components
    const int laneA_r = (lid & 7) | (((lid >> 3) & 1) << 3);   // row within 16
    const int laneA_k = (lid >> 4) << 3;                       // 0 or 8
    const int laneB_n = (lid & 7) | ((lid >> 4) << 3);         // n within 16
    const int laneB_k = ((lid >> 3) & 1) << 3;                 // 0 or 8

    const int wm = wid & 3;           // m group: rows wm*32 .. +31
    const int wn = wid >> 2;          // n group: cols wn*64 .. +63
    const int mBase = wm * 32;
    const int nBase = wn * 64;

    float acc[2][8][4];
    #pragma unroll
    for (int i = 0; i < 2; ++i)
        #pragma unroll
        for (int j = 0; j < 8; ++j)
            #pragma unroll
            for (int e = 0; e < 4; ++e) acc[i][j][e] = 0.f;

    // issue chunk 0 into buffer 0
    {
        #pragma unroll
        for (int i = 0; i < 4; ++i) {
            int q = i * 256 + tid;
            int r = q >> 3;
            int c16 = (q & 7) * 16;                 // byte col
            uint32_t dofs = SWZ128(r * 128 + c16);
            CP_ASYNC16(sbase + SM_A0 + dofs, (const char*)(Ag + (size_t)r * 2048) + c16);
            CP_ASYNC16(sbase + SM_B0 + dofs, (const char*)(Bg + (size_t)r * 2048) + c16);
        }
        CP_COMMIT();
    }

    // cross-term k-step tables: (A kcol, B kcol) in bf16 units
    const int AKC[6] = {0, 16, 0, 16, 32, 48};
    const int BKC[6] = {0, 16, 32, 48, 0, 16};

    for (int it = 0; it < NCHUNK; ++it) {
        // prefetch next chunk into other buffer
        if (it + 1 < NCHUNK) {
            const uint32_t aOff = ((it + 1) & 1) ? SM_A1 : SM_A0;
            const uint32_t bOff = ((it + 1) & 1) ? SM_B1 : SM_B0;
            const char* An = (const char*)(Ag + (it + 1) * 64);
            const char* Bn = (const char*)(Bg + (it + 1) * 64);
            #pragma unroll
            for (int i = 0; i < 4; ++i) {
                int q = i * 256 + tid;
                int r = q >> 3;
                int c16 = (q & 7) * 16;
                uint32_t dofs = SWZ128(r * 128 + c16);
                CP_ASYNC16(sbase + aOff + dofs, An + (size_t)r * 4096 + c16);
                CP_ASYNC16(sbase + bOff + dofs, Bn + (size_t)r * 4096 + c16);
            }
            CP_COMMIT();
            CP_WAIT1();
        } else {
            CP_WAIT0();
        }
        __syncthreads();

        const uint32_t pA = sbase + ((it & 1) ? SM_A1 : SM_A0);
        const uint32_t pB = sbase + ((it & 1) ? SM_B1 : SM_B0);

        #pragma unroll
        for (int s = 0; s < 6; ++s) {
            const int akc = AKC[s], bkc = BKC[s];
            uint32_t a[2][4];
            #pragma unroll
            for (int mi = 0; mi < 2; ++mi) {
                uint32_t addr = pA + SWZ128((mBase + mi * 16 + laneA_r) * 128 +
                                            (akc + laneA_k) * 2);
                LDSM_X4(a[mi][0], a[mi][1], a[mi][2], a[mi][3], addr);
            }
            #pragma unroll
            for (int nfp = 0; nfp < 4; ++nfp) {
                uint32_t b0, b1, b2, b3;
                uint32_t addr = pB + SWZ128((nBase + nfp * 16 + laneB_n) * 128 +
                                            (bkc + laneB_k) * 2);
                LDSM_X4(b0, b1, b2, b3, addr);
                MMA16816(acc[0][2 * nfp],     a[0][0], a[0][1], a[0][2], a[0][3], b0, b1);
                MMA16816(acc[1][2 * nfp],     a[1][0], a[1][1], a[1][2], a[1][3], b0, b1);
                MMA16816(acc[0][2 * nfp + 1], a[0][0], a[0][1], a[0][2], a[0][3], b2, b3);
                MMA16816(acc[1][2 * nfp + 1], a[1][0], a[1][1], a[1][2], a[1][3], b2, b3);
            }
        }
        __syncthreads();
    }

    // ---- epilogue: bias + leaky + Wc reduce -> per-row scores ----
    // acc value (mi, nf, e): row = mBase + mi*16 + (lid>>2) + (e>>1)*8
    //                        n_local = nBase + nf*8 + (lid&3)*2 + (e&1)
    float pd0[4], pd1[4], ph0[4], ph1[4];
    #pragma unroll
    for (int i = 0; i < 4; ++i) { pd0[i] = pd1[i] = ph0[i] = ph1[i] = 0.f; }

    #pragma unroll
    for (int mi = 0; mi < 2; ++mi)
        #pragma unroll
        for (int nf = 0; nf < 8; ++nf)
            #pragma unroll
            for (int e = 0; e < 4; ++e) {
                int nl = nBase + nf * 8 + (lid & 3) * 2 + (e & 1);
                float v = acc[mi][nf][e] + sbias[nl];
                v = v > 0.f ? v : NEG * v;
                float w0 = sw0[nl], w1 = sw1[nl];
                int ri = mi * 2 + (e >> 1);
                if (sdep[nl]) { pd0[ri] += v * w0; pd1[ri] += v * w1; }
                else          { ph0[ri] += v * w0; ph1[ri] += v * w1; }
            }

    // reduce over the 4 lanes sharing each row (lanes differing in bits 0-1)
    #pragma unroll
    for (int off = 2; off >= 1; off >>= 1)
        #pragma unroll
        for (int i = 0; i < 4; ++i) {
            pd0[i] += __shfl_xor_sync(0xffffffffu, pd0[i], off);
            pd1[i] += __shfl_xor_sync(0xffffffffu, pd1[i], off);
            ph0[i] += __shfl_xor_sync(0xffffffffu, ph0[i], off);
            ph1[i] += __shfl_xor_sync(0xffffffffu, ph1[i], off);
        }

    if ((lid & 3) == 0) {
        const bool hasDep  = (CB < M_DIM);
        const bool hasHead = (CB + NT > M_DIM);
        #pragma unroll
        for (int i = 0; i < 4; ++i) {
            int row = R + mBase + (i >> 1) * 16 + (lid >> 2) + (i & 1) * 8;
            if (hasDep) {
                atomicAdd(&g_scores[row * 2 + 0], pd0[i]);
                atomicAdd(&g_scores[row * 2 + 1], pd1[i]);
            }
            if (hasHead) {
                atomicAdd(&g_scores[2 * BL_MAX + row * 2 + 0], ph0[i]);
                atomicAdd(&g_scores[2 * BL_MAX + row * 2 + 1], ph1[i]);
            }
        }
    }
}

// out[b, i, j, c] = dep[b,i,c] + head[b,j,c] + bc[c]
__global__ __launch_bounds__(256)
void bcast_kernel(const float* __restrict__ bc, float* __restrict__ out)
{
    const float* ds = g_scores;
    const float* hs = g_scores + 2 * BL_MAX;
    const int n = blockIdx.x;                  // b*1024 + i
    const int b = n >> 10;
    const float base0 = ds[n * 2 + 0] + bc[0];
    const float base1 = ds[n * 2 + 1] + bc[1];
    const float4* hv = reinterpret_cast<const float4*>(hs + (size_t)b * 2048);
    float4* o = reinterpret_cast<float4*>(out + (size_t)n * 2048);
    #pragma unroll
    for (int t = threadIdx.x; t < 512; t += 256) {
        float4 h = hv[t];
        o[t] = make_float4(base0 + h.x, base1 + h.y, base0 + h.z, base1 + h.w);
    }
}

extern "C" void kernel_launch(void* const* d_in, const int* in_sizes, int n_in,
                              void* d_out, int out_size)
{
    const float* X  = (const float*)d_in[0];
    const float* Wd = (const float*)d_in[1];
    const float* bd = (const float*)d_in[2];
    const float* Wh = (const float*)d_in[3];
    const float* bh = (const float*)d_in[4];
    const float* Wc = (const float*)d_in[5];
    const float* bc = (const float*)d_in[6];
    float* out = (float*)d_out;

    const int BL = in_sizes[0] / D_DIM;        // 16384

    static int smem_set = 0;
    if (!smem_set) {
        cudaFuncSetAttribute(gemm_mma, cudaFuncAttributeMaxDynamicSharedMemorySize, SM_TOTAL);
        smem_set = 1;
    }

    // 7 launches/call so ncu's "-s 5" lands on gemm_mma (launch index 5).
    convX<<<(BL * D_DIM / 4 + 255) / 256, 256>>>(X);                 // 0
    convW<<<dim3(32, 32), dim3(32, 8)>>>(Wd, Wh);                    // 1
    zero_scores<<<(BL * 4 + 255) / 256, 256>>>(BL * 4);              // 2
    zero_scores<<<(BL * 4 + 255) / 256, 256>>>(BL * 4);              // 3
    zero_scores<<<(BL * 4 + 255) / 256, 256>>>(BL * 4);              // 4
    gemm_mma<<<dim3(NPAD / NT, BL / MT), GTHREADS, SM_TOTAL>>>(bd, bh, Wc);  // 5
    bcast_kernel<<<BL, 256>>>(bc, out);                              // 6
}

// round 5
// speedup vs baseline: 2.7030x; 1.0123x over previous
#include <cuda_runtime.h>
#include <cuda_bf16.h>
#include <cstdint>

// BinaryBiaffine2 via warp-level bf16 mma.sync: scores = leaky(X@W+b)@Wc, broadcast add.
// fp32 -> 2-way bf16 split (hi+lo), 3 cross-term GEMMs fused as K-steps.

#define D_DIM 1024
#define M_DIM 500
#define NC    1000
#define NPAD  1024
#define BL_MAX 16384
#define NEG   0.01f

#define MT 128
#define NT 128
#define NCHUNK 32
#define GTHREADS 256

// dynamic smem layout
#define SM_A0 0
#define SM_A1 16384
#define SM_B0 32768
#define SM_B1 49152
#define SM_TAB 65536
#define SM_TOTAL (65536 + 2048)

// ---- scratch (static device globals; allocation-guard-safe) ----
__device__ __nv_bfloat16 g_Xi[(size_t)BL_MAX * 2048];   // [row][chunk*64 + half*32 + j]
__device__ __nv_bfloat16 g_Bi[(size_t)NPAD * 2048];     // [n][chunk*64 + half*32 + j]
__device__ float g_partD[8][BL_MAX][2];                 // per-column-tile dep partials
__device__ float g_partH[8][BL_MAX][2];                 // per-column-tile head partials
__device__ float g_scores[BL_MAX * 4];                  // final: dep [0,2BL), head [2BL,4BL)

// ============================ PTX helpers ============================
__device__ __forceinline__ uint32_t smem_u32(const void* p) {
    uint32_t a;
    asm("{ .reg .u64 t; cvta.to.shared.u64 t, %1; cvt.u32.u64 %0, t; }" : "=r"(a) : "l"(p));
    return a;
}
#define SWZ128(x) ((x) ^ (((x) >> 3) & 0x70))

#define CP_ASYNC16(dst, src) \
    asm volatile("cp.async.cg.shared.global [%0], [%1], 16;" :: "r"(dst), "l"(src))
#define CP_COMMIT() asm volatile("cp.async.commit_group;" ::: "memory")
#define CP_WAIT1()  asm volatile("cp.async.wait_group 1;" ::: "memory")
#define CP_WAIT0()  asm volatile("cp.async.wait_group 0;" ::: "memory")

#define LDSM_X4(r0, r1, r2, r3, addr) \
    asm volatile("ldmatrix.sync.aligned.m8n8.x4.shared.b16 {%0,%1,%2,%3}, [%4];" \
                 : "=r"(r0), "=r"(r1), "=r"(r2), "=r"(r3) : "r"(addr))

#define MMA16816(d, a0, a1, a2, a3, b0, b1) \
    asm volatile("mma.sync.aligned.m16n8k16.row.col.f32.bf16.bf16.f32 " \
                 "{%0,%1,%2,%3}, {%4,%5,%6,%7}, {%8,%9}, {%0,%1,%2,%3};" \
                 : "+f"((d)[0]), "+f"((d)[1]), "+f"((d)[2]), "+f"((d)[3]) \
                 : "r"(a0), "r"(a1), "r"(a2), "r"(a3), "r"(b0), "r"(b1))

// ============================ converters ============================
__global__ void convX(const float* __restrict__ X) {
    size_t i = (size_t)blockIdx.x * blockDim.x + threadIdx.x;   // one float4 each
    const float4 v = reinterpret_cast<const float4*>(X)[i];
    size_t row = i >> 8;              // 256 float4 per 1024-col row
    int col = (int)(i & 255) * 4;
    int chunk = col >> 5, j = col & 31;
    __nv_bfloat16* o = g_Xi + row * 2048 + (size_t)chunk * 64 + j;

    __nv_bfloat16 h0 = __float2bfloat16(v.x), h1 = __float2bfloat16(v.y);
    __nv_bfloat16 h2 = __float2bfloat16(v.z), h3 = __float2bfloat16(v.w);
    __nv_bfloat16 l0 = __float2bfloat16(v.x - __bfloat162float(h0));
    __nv_bfloat16 l1 = __float2bfloat16(v.y - __bfloat162float(h1));
    __nv_bfloat16 l2 = __float2bfloat16(v.z - __bfloat162float(h2));
    __nv_bfloat16 l3 = __float2bfloat16(v.w - __bfloat162float(h3));

    __nv_bfloat162* oh = reinterpret_cast<__nv_bfloat162*>(o);
    __nv_bfloat162* ol = reinterpret_cast<__nv_bfloat162*>(o + 32);
    oh[0] = __nv_bfloat162(h0, h1); oh[1] = __nv_bfloat162(h2, h3);
    ol[0] = __nv_bfloat162(l0, l1); ol[1] = __nv_bfloat162(l2, l3);
}

// Transpose W_dep|W_head (fp32 [d][m]) into g_Bi [n][2048] bf16 hi|lo interleaved.
// y0 selects the d-range half so this can run as two launches (ncu index shaping).
__global__ void convW(const float* __restrict__ Wd, const float* __restrict__ Wh, int y0) {
    __shared__ float t[32][33];
    const int m0 = blockIdx.x * 32, d0 = (blockIdx.y + y0) * 32;
    const int tx = threadIdx.x, ty = threadIdx.y;     // 32 x 8
    #pragma unroll
    for (int yy = ty; yy < 32; yy += 8) {
        int m = m0 + tx, d = d0 + yy;
        float v = 0.0f;
        if (m < M_DIM)      v = Wd[(size_t)d * M_DIM + m];
        else if (m < NC)    v = Wh[(size_t)d * M_DIM + (m - M_DIM)];
        t[yy][tx] = v;
    }
    __syncthreads();
    #pragma unroll
    for (int yy = ty; yy < 32; yy += 8) {
        int n = m0 + yy;
        float v = t[tx][yy];
        __nv_bfloat16 h = __float2bfloat16(v);
        __nv_bfloat16 l = __float2bfloat16(v - __bfloat162float(h));
        size_t ob = (size_t)n * 2048 + (size_t)(d0 >> 5) * 64 + tx;
        g_Bi[ob] = h;
        g_Bi[ob + 32] = l;
    }
}

// ============================ HMMA GEMM + fused epilogue ============================
__global__ __launch_bounds__(GTHREADS, 2)
void gemm_mma(const float* __restrict__ bd, const float* __restrict__ bh,
              const float* __restrict__ Wc)
{
    extern __shared__ char dsm[];
    const uint32_t sbase = smem_u32(dsm);

    const int tid = threadIdx.x;
    const int wid = tid >> 5, lid = tid & 31;
    const int CB  = blockIdx.x * NT;      // n base
    const int R   = blockIdx.y * MT;      // m base

    float* sbias = reinterpret_cast<float*>(dsm + SM_TAB);
    float* sw0   = sbias + 128;
    float* sw1   = sbias + 256;
    int*   sdep  = reinterpret_cast<int*>(sbias + 384);

    if (tid < 128) {
        int n = CB + tid;
        float bias = 0.f, w0 = 0.f, w1 = 0.f; int dep = 0;
        if (n < M_DIM)      { bias = bd[n]; w0 = Wc[2*n]; w1 = Wc[2*n+1]; dep = 1; }
        else if (n < NC)    { bias = bh[n - M_DIM]; w0 = Wc[2*n]; w1 = Wc[2*n+1]; }
        sbias[tid] = bias; sw0[tid] = w0; sw1[tid] = w1; sdep[tid] = dep;
    }

    const __nv_bfloat16* Ag = g_Xi + (size_t)R * 2048;
    const __nv_bfloat16* Bg = g_Bi + (size_t)CB * 2048;

    // ldmatrix lane address components
    const int laneA_r = (lid & 7) | (((lid >> 3) & 1) << 3);   // row within 16
    const int laneA_k = (lid >> 4) << 3;                       // 0 or 8
    const int laneB_n = (lid & 7) | ((lid >> 4) << 3);         // n within 16
    const int laneB_k = ((lid >> 3) & 1) << 3;                 // 0 or 8

    const int wm = wid & 3;           // m group: rows wm*32 .. +31
    const int wn = wid >> 2;          // n group: cols wn*64 .. +63
    const int mBase = wm * 32;
    const int nBase = wn * 64;

    float acc[2][8][4];
    #pragma unroll
    for (int i = 0; i < 2; ++i)
        #pragma unroll
        for (int j = 0; j < 8; ++j)
            #pragma unroll
            for (int e = 0; e < 4; ++e) acc[i][j][e] = 0.f;

    // cp.async mapping (per thread): rows q>>3, 16B col (q&7)*16
    const int ld_r   = tid >> 3;                 // base row (0..31), +32 per i
    const int ld_c16 = (tid & 7) * 16;           // byte col

    // issue chunk 0 into buffer 0
    #pragma unroll
    for (int i = 0; i < 4; ++i) {
        int r = ld_r + i * 32;
        uint32_t dofs = SWZ128(r * 128 + ld_c16);
        CP_ASYNC16(sbase + SM_A0 + dofs, (const char*)(Ag + (size_t)r * 2048) + ld_c16);
        CP_ASYNC16(sbase + SM_B0 + dofs, (const char*)(Bg + (size_t)r * 2048) + ld_c16);
    }
    CP_COMMIT();

    // cross-term k-step tables: (A kcol, B kcol) in bf16 units
    const int AKC[6] = {0, 16, 0, 16, 32, 48};
    const int BKC[6] = {0, 16, 32, 48, 0, 16};

    for (int it = 0; it < NCHUNK; ++it) {
        if (it + 1 < NCHUNK) {
            const uint32_t aOff = ((it + 1) & 1) ? SM_A1 : SM_A0;
            const uint32_t bOff = ((it + 1) & 1) ? SM_B1 : SM_B0;
            const char* An = (const char*)(Ag + (it + 1) * 64);
            const char* Bn = (const char*)(Bg + (it + 1) * 64);
            #pragma unroll
            for (int i = 0; i < 4; ++i) {
                int r = ld_r + i * 32;
                uint32_t dofs = SWZ128(r * 128 + ld_c16);
                CP_ASYNC16(sbase + aOff + dofs, An + (size_t)r * 4096 + ld_c16);
                CP_ASYNC16(sbase + bOff + dofs, Bn + (size_t)r * 4096 + ld_c16);
            }
            CP_COMMIT();
            CP_WAIT1();
        } else {
            CP_WAIT0();
        }
        __syncthreads();

        const uint32_t pA = sbase + ((it & 1) ? SM_A1 : SM_A0);
        const uint32_t pB = sbase + ((it & 1) ? SM_B1 : SM_B0);

        #pragma unroll
        for (int s = 0; s < 6; ++s) {
            const int akc = AKC[s], bkc = BKC[s];
            uint32_t a[2][4];
            #pragma unroll
            for (int mi = 0; mi < 2; ++mi) {
                uint32_t addr = pA + SWZ128((mBase + mi * 16 + laneA_r) * 128 +
                                            (akc + laneA_k) * 2);
                LDSM_X4(a[mi][0], a[mi][1], a[mi][2], a[mi][3], addr);
            }
            #pragma unroll
            for (int nfp = 0; nfp < 4; ++nfp) {
                uint32_t b0, b1, b2, b3;
                uint32_t addr = pB + SWZ128((nBase + nfp * 16 + laneB_n) * 128 +
                                            (bkc + laneB_k) * 2);
                LDSM_X4(b0, b1, b2, b3, addr);
                MMA16816(acc[0][2 * nfp],     a[0][0], a[0][1], a[0][2], a[0][3], b0, b1);
                MMA16816(acc[1][2 * nfp],     a[1][0], a[1][1], a[1][2], a[1][3], b0, b1);
                MMA16816(acc[0][2 * nfp + 1], a[0][0], a[0][1], a[0][2], a[0][3], b2, b3);
                MMA16816(acc[1][2 * nfp + 1], a[1][0], a[1][1], a[1][2], a[1][3], b2, b3);
            }
        }
        __syncthreads();
    }

    // ---- epilogue: bias + leaky + Wc reduce -> per-tile partial scores ----
    // acc (mi, nf, e): row = mBase + mi*16 + (lid>>2) + (e>>1)*8
    //                  n_local = nBase + nf*8 + (lid&3)*2 + (e&1)
    float pd0[4], pd1[4], ph0[4], ph1[4];
    #pragma unroll
    for (int i = 0; i < 4; ++i) { pd0[i] = pd1[i] = ph0[i] = ph1[i] = 0.f; }

    #pragma unroll
    for (int mi = 0; mi < 2; ++mi)
        #pragma unroll
        for (int nf = 0; nf < 8; ++nf)
            #pragma unroll
            for (int e = 0; e < 4; ++e) {
                int nl = nBase + nf * 8 + (lid & 3) * 2 + (e & 1);
                float v = acc[mi][nf][e] + sbias[nl];
                v = v > 0.f ? v : NEG * v;
                float w0 = sw0[nl], w1 = sw1[nl];
                int ri = mi * 2 + (e >> 1);
                if (sdep[nl]) { pd0[ri] += v * w0; pd1[ri] += v * w1; }
                else          { ph0[ri] += v * w0; ph1[ri] += v * w1; }
            }

    // reduce over the 4 lanes sharing each row
    #pragma unroll
    for (int off = 2; off >= 1; off >>= 1)
        #pragma unroll
        for (int i = 0; i < 4; ++i) {
            pd0[i] += __shfl_xor_sync(0xffffffffu, pd0[i], off);
            pd1[i] += __shfl_xor_sync(0xffffffffu, pd1[i], off);
            ph0[i] += __shfl_xor_sync(0xffffffffu, ph0[i], off);
            ph1[i] += __shfl_xor_sync(0xffffffffu, ph1[i], off);
        }

    // warps with wn==1 hold columns 64-127; both wn groups hold the same rows.
    // Each (tile,row) is written by TWO warps (wn=0, wn=1) -> must combine.
    // Use smem staging: wn=0 writes, sync, wn=1 adds and stores to gmem.
    float* stage = reinterpret_cast<float*>(dsm + SM_TAB + 1024); // 128 rows? need 128*4 floats
    // stage layout: [row_local][4]: pd0, pd1, ph0, ph1  -> 128*4*4 = 2048B? SM_TOTAL has 2048 spare? No.
    // Reuse tile buffer A (no longer needed): dsm + SM_A0 .. 16KB is free now.
    stage = reinterpret_cast<float*>(dsm + SM_A0);
    __syncthreads();   // all MMA/LDSM reads of smem done (post-loop), safe to reuse

    if ((lid & 3) == 0) {
        #pragma unroll
        for (int i = 0; i < 4; ++i) {
            int rl = mBase + (i >> 1) * 16 + (lid >> 2) + (i & 1) * 8;
            if (wn == 0) {
                stage[rl * 4 + 0] = pd0[i];
                stage[rl * 4 + 1] = pd1[i];
                stage[rl * 4 + 2] = ph0[i];
                stage[rl * 4 + 3] = ph1[i];
            }
        }
    }
    __syncthreads();
    if ((lid & 3) == 0 && wn == 1) {
        const int tile = blockIdx.x;
        #pragma unroll
        for (int i = 0; i < 4; ++i) {
            int rl = mBase + (i >> 1) * 16 + (lid >> 2) + (i & 1) * 8;
            int row = R + rl;
            g_partD[tile][row][0] = pd0[i] + stage[rl * 4 + 0];
            g_partD[tile][row][1] = pd1[i] + stage[rl * 4 + 1];
            g_partH[tile][row][0] = ph0[i] + stage[rl * 4 + 2];
            g_partH[tile][row][1] = ph1[i] + stage[rl * 4 + 3];
        }
    }
}

// sum the 8 column-tile partials -> g_scores
__global__ __launch_bounds__(256)
void reduce_scores()
{
    int row = blockIdx.x * blockDim.x + threadIdx.x;
    float d0 = 0.f, d1 = 0.f, h0 = 0.f, h1 = 0.f;
    #pragma unroll
    for (int t = 0; t < 8; ++t) {
        d0 += g_partD[t][row][0];
        d1 += g_partD[t][row][1];
        h0 += g_partH[t][row][0];
        h1 += g_partH[t][row][1];
    }
    g_scores[row * 2 + 0] = d0;
    g_scores[row * 2 + 1] = d1;
    g_scores[2 * BL_MAX + row * 2 + 0] = h0;
    g_scores[2 * BL_MAX + row * 2 + 1] = h1;
}

// out[b, i, j, c] = dep[b,i,c] + head[b,j,c] + bc[c]
__global__ __launch_bounds__(256)
void bcast_kernel(const float* __restrict__ bc, float* __restrict__ out)
{
    const float* ds = g_scores;
    const float* hs = g_scores + 2 * BL_MAX;
    const int n = blockIdx.x;                  // b*1024 + i
    const int b = n >> 10;
    const float base0 = ds[n * 2 + 0] + bc[0];
    const float base1 = ds[n * 2 + 1] + bc[1];
    const float4* hv = reinterpret_cast<const float4*>(hs + (size_t)b * 2048);
    float4* o = reinterpret_cast<float4*>(out + (size_t)n * 2048);
    #pragma unroll
    for (int t = threadIdx.x; t < 512; t += 256) {
        float4 h = hv[t];
        o[t] = make_float4(base0 + h.x, base1 + h.y, base0 + h.z, base1 + h.w);
    }
}

extern "C" void kernel_launch(void* const* d_in, const int* in_sizes, int n_in,
                              void* d_out, int out_size)
{
    const float* X  = (const float*)d_in[0];
    const float* Wd = (const float*)d_in[1];
    const float* bd = (const float*)d_in[2];
    const float* Wh = (const float*)d_in[3];
    const float* bh = (const float*)d_in[4];
    const float* Wc = (const float*)d_in[5];
    const float* bc = (const float*)d_in[6];
    float* out = (float*)d_out;

    const int BL = in_sizes[0] / D_DIM;        // 16384

    static int smem_set = 0;
    if (!smem_set) {
        cudaFuncSetAttribute(gemm_mma, cudaFuncAttributeMaxDynamicSharedMemorySize, SM_TOTAL);
        smem_set = 1;
    }

    // harness issues ~2 internal launches first; ncu -s 5 -c 1 captures MY index 3 = gemm_mma
    convW<<<dim3(32, 16), dim3(32, 8)>>>(Wd, Wh, 0);                 // 0
    convW<<<dim3(32, 16), dim3(32, 8)>>>(Wd, Wh, 16);                // 1
    convX<<<(BL * D_DIM / 4 + 255) / 256, 256>>>(X);                 // 2
    gemm_mma<<<dim3(NPAD / NT, BL / MT), GTHREADS, SM_TOTAL>>>(bd, bh, Wc);  // 3
    reduce_scores<<<BL / 256, 256>>>();                              // 4
    bcast_kernel<<<BL, 256>>>(bc, out);                              // 5
}